// round 11
// baseline (speedup 1.0000x reference)
#include <cuda_runtime.h>
#include <cuda_fp16.h>
#include <cstdint>

// ---------------- problem constants ----------------
#define TTOK   65536           // B*L
#define HD     256
#define KD     1536            // 6*H
#define ND     1536            // 6 gates * H, n = h*6+g
#define LMASK  2047
#define OUT_HALF 16777216ull   // TTOK*HD

// ---------------- tiling ----------------
#define BM      128
#define BN      96
#define NT      16             // ND / BN
#define MT      512            // TTOK / BM
#define BK      64             // fp16 k elems per tile (128 B)
#define KITERS  24             // KD / BK
#define STAGES  3
#define NTHREADS 256
#define ROWB    144            // bytes per smem row (64 fp16 + 16 pad)
#define A_BYTES (BM*ROWB)      // 18432
#define B_BYTES (BN*ROWB)      // 13824
#define STAGE_BYTES (A_BYTES + B_BYTES)     // 32256
#define GSTRIDE 98             // gates staging row stride (floats)
#define BIAS_BYTE_OFF (STAGES*STAGE_BYTES)  // 96768
#define SMEM_TOTAL (BIAS_BYTE_OFF + 6144)   // 102912 bytes (2 CTAs/SM)

__device__ __half g_Wh[(size_t)ND * KD];          // [n][k], n-major fp16
__device__ __half g_af[4ull * TTOK * HD];         // fp16: h_t, x, h_slot, h_intent

__device__ __forceinline__ uint32_t h2_to_u32(__half2 v) {
    union { __half2 h; uint32_t u; } cvt;
    cvt.h = v;
    return cvt.u;
}

// ---------------- merged prep ----------------
#define A_BLOCKS 32768         // 4 tensors * 8192
#define W_BLOCKS 288           // 6 g * 24 ktiles * 2 hhalves

__global__ __launch_bounds__(256) void prep_kernel(
    const float* __restrict__ Ws,
    const float* __restrict__ h_t, const float* __restrict__ x,
    const float* __restrict__ h_slot, const float* __restrict__ h_intent)
{
    __shared__ float s[64][133];
    const int bid = blockIdx.x;
    const int tid = threadIdx.x;
    if (bid < A_BLOCKS) {
        const int which = bid >> 13;           // 0..3
        const float* src = (which == 0) ? h_t : (which == 1) ? x
                         : (which == 2) ? h_slot : h_intent;
        __half* dst = g_af + (size_t)which * (TTOK * HD);
        const size_t i = (((size_t)(bid & 8191)) * 256 + tid) * 8;
        float4 v0 = *(const float4*)(src + i);
        float4 v1 = *(const float4*)(src + i + 4);
        uint4 pk = make_uint4(h2_to_u32(__floats2half2_rn(v0.x, v0.y)),
                              h2_to_u32(__floats2half2_rn(v0.z, v0.w)),
                              h2_to_u32(__floats2half2_rn(v1.x, v1.y)),
                              h2_to_u32(__floats2half2_rn(v1.z, v1.w)));
        *(uint4*)(dst + i) = pk;
    } else {
        const int bw = bid - A_BLOCKS;         // 0..287
        const int g  = bw / 48;
        const int rem = bw - g * 48;
        const int kt = rem >> 1;
        const int k0 = kt * 64;
        const int h0 = (rem & 1) * 128;
#pragma unroll
        for (int p = 0; p < 8; p++) {
            int i  = tid + p * 256;
            int k  = i >> 5;
            int f4 = i & 31;
            float4 v = *(const float4*)(Ws + ((size_t)g * KD + k0 + k) * HD + h0 + f4 * 4);
            s[k][f4 * 4 + 0] = v.x;
            s[k][f4 * 4 + 1] = v.y;
            s[k][f4 * 4 + 2] = v.z;
            s[k][f4 * 4 + 3] = v.w;
        }
        __syncthreads();
        const int lane = tid & 31;
        const int wrow = tid >> 5;
#pragma unroll
        for (int p = 0; p < 16; p++) {
            int h = wrow + p * 8;
            int n = (h0 + h) * 6 + g;
            __half2 v = __floats2half2_rn(s[2 * lane][h], s[2 * lane + 1][h]);
            *(__half2*)(g_Wh + (size_t)n * KD + k0 + 2 * lane) = v;
        }
    }
}

// ---------------- helpers ----------------
__device__ __forceinline__ void cp16(uint32_t dst, const void* src, uint32_t sz) {
    asm volatile("cp.async.ca.shared.global [%0], [%1], 16, %2;\n"
                 :: "r"(dst), "l"(src), "r"(sz));
}
__device__ __forceinline__ void cp16f(uint32_t dst, const void* src) {
    asm volatile("cp.async.ca.shared.global [%0], [%1], 16;\n"
                 :: "r"(dst), "l"(src));
}
__device__ __forceinline__ void ldsm4(uint32_t& r0, uint32_t& r1, uint32_t& r2,
                                      uint32_t& r3, uint32_t addr) {
    asm volatile("ldmatrix.sync.aligned.m8n8.x4.shared.b16 {%0,%1,%2,%3}, [%4];"
                 : "=r"(r0), "=r"(r1), "=r"(r2), "=r"(r3) : "r"(addr));
}
__device__ __forceinline__ float fsig(float v)  { return 1.0f / (1.0f + __expf(-v)); }
__device__ __forceinline__ float ftanh(float v) { return 1.0f - 2.0f / (__expf(2.0f * v) + 1.0f); }

__global__ __launch_bounds__(NTHREADS, 2) void slstm_kernel(
    const float* __restrict__ c_t, const float* __restrict__ bs,
    float* __restrict__ out)
{
    extern __shared__ float smem[];
    const int tid  = threadIdx.x;
    const int warp = tid >> 5;
    const int lane = tid & 31;
    const int wr = warp & 3;           // 4 warp rows (M, 32 each)
    const int wc = warp >> 2;          // 2 warp cols (N, 48 each)
    const int gID = lane >> 2;
    const int t4  = lane & 3;
    const int rowb = blockIdx.y * BM;
    const int nb   = blockIdx.x * BN;
    const int h0t  = blockIdx.x * 16;

    const uint32_t sb = (uint32_t)__cvta_generic_to_shared(smem);

    // bias preload
    {
        float4* bbuf = (float4*)((char*)smem + BIAS_BYTE_OFF);
        const float4* src = (const float4*)bs;
        for (int i = tid; i < 384; i += NTHREADS) bbuf[i] = src[i];
    }

    float acc[2][6][4];
#pragma unroll
    for (int i = 0; i < 2; i++)
#pragma unroll
        for (int j = 0; j < 6; j++)
#pragma unroll
            for (int q = 0; q < 4; q++) acc[i][j][q] = 0.0f;

    auto issue = [&](int kt) {
        const int s = kt % STAGES;
        const uint32_t sA = sb + (uint32_t)(s * STAGE_BYTES);
        const uint32_t sB = sA + A_BYTES;
        const int chunk = kt >> 2;             // 4 k-tiles per 256-wide chunk
        const int j0 = (kt & 3) * 64;
        const int which = (chunk <= 2) ? 0 : (chunk - 2);
        const __half* abase = g_af + (size_t)which * (TTOK * HD);
        const int shift = (chunk == 1) ? -1 : (chunk == 2) ? 1 : 0;
        const int mode  = (chunk == 1) ? 1 : (chunk == 2) ? 2 : 0;
#pragma unroll
        for (int i = 0; i < 4; i++) {          // A: 1024 16B chunks
            int idx = tid + i * NTHREADS;
            int r  = idx >> 3;
            int f4 = idx & 7;
            int t  = rowb + r;
            int l  = t & LMASK;
            bool valid = (mode == 0) || (mode == 1 ? (l != 0) : (l != LMASK));
            const __half* src = valid ? (abase + (size_t)(t + shift) * HD + j0 + f4 * 8)
                                      : abase;   // src-size=0 -> zero fill
            cp16(sA + (uint32_t)(r * ROWB + f4 * 16), src, valid ? 16u : 0u);
        }
        const __half* wbase = g_Wh + (size_t)nb * KD + kt * BK;
#pragma unroll
        for (int i = 0; i < 3; i++) {          // B: 768 16B chunks
            int idx = tid + i * NTHREADS;
            int r  = idx >> 3;
            int f4 = idx & 7;
            cp16f(sB + (uint32_t)(r * ROWB + f4 * 16),
                  wbase + (size_t)r * KD + f4 * 8);
        }
        asm volatile("cp.async.commit_group;\n");
    };

    issue(0);
    issue(1);

    // ldmatrix lane addressing
    const int lj = lane >> 3;
    const int ls = lane & 7;
    const uint32_t a_lane_off =
        (uint32_t)((wr * 32 + (lj & 1) * 8 + ls) * ROWB + (lj >> 1) * 16);
    const uint32_t b_lane_off =
        (uint32_t)((wc * 48 + (lj & 1) * 8 + ls) * ROWB + (lj >> 1) * 16);

#pragma unroll 1
    for (int kt = 0; kt < KITERS; ++kt) {
        asm volatile("cp.async.wait_group 1;\n");
        __syncthreads();
        if (kt + 2 < KITERS) issue(kt + 2);
        else asm volatile("cp.async.commit_group;\n");

        const int st = kt % STAGES;
        const uint32_t aA = sb + (uint32_t)(st * STAGE_BYTES) + a_lane_off;
        const uint32_t aB = sb + (uint32_t)(st * STAGE_BYTES) + A_BYTES + b_lane_off;

        uint32_t a[2][2][4], b[2][6][2];   // [buf][tile][regs]
#pragma unroll
        for (int mt = 0; mt < 2; mt++)
            ldsm4(a[0][mt][0], a[0][mt][1], a[0][mt][2], a[0][mt][3],
                  aA + (uint32_t)(mt * 16 * ROWB));
#pragma unroll
        for (int bt = 0; bt < 3; bt++) {
            uint32_t r0, r1, r2, r3;
            ldsm4(r0, r1, r2, r3, aB + (uint32_t)(bt * 16 * ROWB));
            b[0][2 * bt][0] = r0; b[0][2 * bt + 1][0] = r1;
            b[0][2 * bt][1] = r2; b[0][2 * bt + 1][1] = r3;
        }

#pragma unroll
        for (int ks = 0; ks < 4; ++ks) {       // four k16 steps per BK=64
            const int cur = ks & 1;
            const int nxt = cur ^ 1;
            if (ks < 3) {
                const uint32_t ko = (uint32_t)((ks + 1) * 32);
#pragma unroll
                for (int mt = 0; mt < 2; mt++)
                    ldsm4(a[nxt][mt][0], a[nxt][mt][1], a[nxt][mt][2], a[nxt][mt][3],
                          aA + (uint32_t)(mt * 16 * ROWB) + ko);
#pragma unroll
                for (int bt = 0; bt < 3; bt++) {
                    uint32_t r0, r1, r2, r3;
                    ldsm4(r0, r1, r2, r3, aB + (uint32_t)(bt * 16 * ROWB) + ko);
                    b[nxt][2 * bt][0] = r0; b[nxt][2 * bt + 1][0] = r1;
                    b[nxt][2 * bt][1] = r2; b[nxt][2 * bt + 1][1] = r3;
                }
            }
#pragma unroll
            for (int mt = 0; mt < 2; mt++)
#pragma unroll
                for (int nt = 0; nt < 6; nt++) {
                    asm volatile(
                        "mma.sync.aligned.m16n8k16.row.col.f32.f16.f16.f32 "
                        "{%0,%1,%2,%3}, {%4,%5,%6,%7}, {%8,%9}, {%0,%1,%2,%3};\n"
                        : "+f"(acc[mt][nt][0]), "+f"(acc[mt][nt][1]),
                          "+f"(acc[mt][nt][2]), "+f"(acc[mt][nt][3])
                        : "r"(a[cur][mt][0]), "r"(a[cur][mt][1]),
                          "r"(a[cur][mt][2]), "r"(a[cur][mt][3]),
                          "r"(b[cur][nt][0]), "r"(b[cur][nt][1]));
                }
        }
    }

    asm volatile("cp.async.wait_group 0;\n");
    __syncthreads();

    // stage accumulators: gates[r][h_local*6+g] (128 rows x 96 cols)
    float* gs = smem;
#pragma unroll
    for (int mt = 0; mt < 2; mt++) {
#pragma unroll
        for (int nt = 0; nt < 6; nt++) {
            int r = wr * 32 + mt * 16 + gID;
            int c = wc * 48 + nt * 8 + t4 * 2;
            *(float2*)(gs + r       * GSTRIDE + c) = make_float2(acc[mt][nt][0], acc[mt][nt][1]);
            *(float2*)(gs + (r + 8) * GSTRIDE + c) = make_float2(acc[mt][nt][2], acc[mt][nt][3]);
        }
    }
    __syncthreads();

    // fused epilogue: each warp: 16 rows x 16 h; per iter 2 rows (lane>>4), 16 h (lane&15)
    const float* bb = (const float*)((char*)smem + BIAS_BYTE_OFF);
    const int hl = lane & 15;
    const int rr = lane >> 4;
    const int h = h0t + hl;
#pragma unroll 1
    for (int it = 0; it < 8; it++) {
        const int r = warp * 16 + it * 2 + rr;
        const int t = rowb + r;
        const int l = t & LMASK;
        const float* gp = gs + r * GSTRIDE + hl * 6;
        float I  = fsig(gp[0] + bb[h]);
        float O  = fsig(gp[1] + bb[256  + h]);
        float F  = fsig(gp[2] + bb[512  + h]);
        float Lg = fsig(gp[3] + bb[768  + h]);
        float R  = fsig(gp[4] + bb[1024 + h]);
        float U  = ftanh(gp[5] + bb[1280 + h]);
        float cm = c_t[(size_t)t * HD + h];
        float cl = (l != 0)     ? c_t[(size_t)(t - 1) * HD + h] : 0.0f;
        float cr = (l != LMASK) ? c_t[(size_t)(t + 1) * HD + h] : 0.0f;
        float ei = __expf(I), ef = __expf(F), el = __expf(Lg), er = __expf(R);
        float inv = 1.0f / (ei + ef + el + er);
        float c = (ef * cm + el * cl + er * cr + ei * U) * inv;
        float hn = O * ftanh(c);
        out[(size_t)t * HD + h] = hn;
        out[OUT_HALF + (size_t)t * HD + h] = c;
    }
}

// ---------------- launch ----------------
extern "C" void kernel_launch(void* const* d_in, const int* in_sizes, int n_in,
                              void* d_out, int out_size) {
    (void)in_sizes; (void)n_in; (void)out_size;
    const float* h_t      = (const float*)d_in[0];
    const float* x        = (const float*)d_in[1];
    const float* h_slot   = (const float*)d_in[2];
    const float* h_intent = (const float*)d_in[3];
    const float* c_t      = (const float*)d_in[4];
    const float* Ws       = (const float*)d_in[5];
    const float* bs       = (const float*)d_in[6];
    float* out = (float*)d_out;

    cudaFuncSetAttribute(slstm_kernel, cudaFuncAttributeMaxDynamicSharedMemorySize,
                         SMEM_TOTAL);

    prep_kernel<<<A_BLOCKS + W_BLOCKS, 256>>>(Ws, h_t, x, h_slot, h_intent);
    slstm_kernel<<<dim3(NT, MT), NTHREADS, SMEM_TOTAL>>>(c_t, bs, out);
}

// round 12
// speedup vs baseline: 1.1783x; 1.1783x over previous
#include <cuda_runtime.h>
#include <cuda_fp16.h>
#include <cstdint>

// ---------------- problem constants ----------------
#define TTOK   65536           // B*L
#define HD     256
#define KD     1536            // 6*H
#define ND     1536            // 6 gates * H, n = h*6+g
#define LMASK  2047
#define OUT_HALF 16777216ull   // TTOK*HD

// ---------------- tiling ----------------
#define BM      128
#define BN      192
#define NT      8              // ND / BN
#define MT      512            // TTOK / BM
#define BK      64             // fp16 k elems per tile (128 B)
#define KITERS  24             // KD / BK
#define STAGES  3
#define NTHREADS 512
#define ROWB    144            // bytes per smem row (64 fp16 + 16 pad)
#define A_BYTES (BM*ROWB)      // 18432
#define B_BYTES (BN*ROWB)      // 27648
#define STAGE_BYTES (A_BYTES + B_BYTES)     // 46080
#define GSTRIDE 194            // gates staging row stride (floats)
#define BIAS_BYTE_OFF (STAGES*STAGE_BYTES)  // 138240
#define SMEM_TOTAL (BIAS_BYTE_OFF + 6144)   // 144384 bytes

__device__ __half g_Wh[(size_t)ND * KD];          // [n][k], n-major fp16
__device__ __half g_af[4ull * TTOK * HD];         // fp16: h_t, x, h_slot, h_intent

__device__ __forceinline__ uint32_t h2_to_u32(__half2 v) {
    union { __half2 h; uint32_t u; } cvt;
    cvt.h = v;
    return cvt.u;
}

// ---------------- merged prep ----------------
#define A_BLOCKS 32768         // 4 tensors * 8192
#define W_BLOCKS 288           // 6 g * 24 ktiles * 2 hhalves

__global__ __launch_bounds__(256) void prep_kernel(
    const float* __restrict__ Ws,
    const float* __restrict__ h_t, const float* __restrict__ x,
    const float* __restrict__ h_slot, const float* __restrict__ h_intent)
{
    __shared__ float s[64][133];
    const int bid = blockIdx.x;
    const int tid = threadIdx.x;
    if (bid < A_BLOCKS) {
        const int which = bid >> 13;           // 0..3
        const float* src = (which == 0) ? h_t : (which == 1) ? x
                         : (which == 2) ? h_slot : h_intent;
        __half* dst = g_af + (size_t)which * (TTOK * HD);
        const size_t i = (((size_t)(bid & 8191)) * 256 + tid) * 8;
        float4 v0 = *(const float4*)(src + i);
        float4 v1 = *(const float4*)(src + i + 4);
        uint4 pk = make_uint4(h2_to_u32(__floats2half2_rn(v0.x, v0.y)),
                              h2_to_u32(__floats2half2_rn(v0.z, v0.w)),
                              h2_to_u32(__floats2half2_rn(v1.x, v1.y)),
                              h2_to_u32(__floats2half2_rn(v1.z, v1.w)));
        *(uint4*)(dst + i) = pk;
    } else {
        const int bw = bid - A_BLOCKS;         // 0..287
        const int g  = bw / 48;
        const int rem = bw - g * 48;
        const int kt = rem >> 1;
        const int k0 = kt * 64;
        const int h0 = (rem & 1) * 128;
#pragma unroll
        for (int p = 0; p < 8; p++) {
            int i  = tid + p * 256;
            int k  = i >> 5;
            int f4 = i & 31;
            float4 v = *(const float4*)(Ws + ((size_t)g * KD + k0 + k) * HD + h0 + f4 * 4);
            s[k][f4 * 4 + 0] = v.x;
            s[k][f4 * 4 + 1] = v.y;
            s[k][f4 * 4 + 2] = v.z;
            s[k][f4 * 4 + 3] = v.w;
        }
        __syncthreads();
        const int lane = tid & 31;
        const int wrow = tid >> 5;
#pragma unroll
        for (int p = 0; p < 16; p++) {
            int h = wrow + p * 8;
            int n = (h0 + h) * 6 + g;
            __half2 v = __floats2half2_rn(s[2 * lane][h], s[2 * lane + 1][h]);
            *(__half2*)(g_Wh + (size_t)n * KD + k0 + 2 * lane) = v;
        }
    }
}

// ---------------- helpers ----------------
__device__ __forceinline__ void cp16(uint32_t dst, const void* src, uint32_t sz) {
    asm volatile("cp.async.ca.shared.global [%0], [%1], 16, %2;\n"
                 :: "r"(dst), "l"(src), "r"(sz));
}
__device__ __forceinline__ void cp16f(uint32_t dst, const void* src) {
    asm volatile("cp.async.ca.shared.global [%0], [%1], 16;\n"
                 :: "r"(dst), "l"(src));
}
__device__ __forceinline__ void ldsm4(uint32_t& r0, uint32_t& r1, uint32_t& r2,
                                      uint32_t& r3, uint32_t addr) {
    asm volatile("ldmatrix.sync.aligned.m8n8.x4.shared.b16 {%0,%1,%2,%3}, [%4];"
                 : "=r"(r0), "=r"(r1), "=r"(r2), "=r"(r3) : "r"(addr));
}
__device__ __forceinline__ float tanh_fast(float x) {
    float y;
    asm("tanh.approx.f32 %0, %1;" : "=f"(y) : "f"(x));
    return y;
}
__device__ __forceinline__ float fsig(float v)  { return 0.5f * tanh_fast(0.5f * v) + 0.5f; }

__global__ __launch_bounds__(NTHREADS, 1) void slstm_kernel(
    const float* __restrict__ c_t, const float* __restrict__ bs,
    float* __restrict__ out)
{
    extern __shared__ float smem[];
    const int tid  = threadIdx.x;
    const int warp = tid >> 5;
    const int lane = tid & 31;
    const int wr = warp & 3;           // 4 warp rows (M, 32 each)
    const int wc = warp >> 2;          // 4 warp cols (N, 48 each)
    const int gID = lane >> 2;
    const int t4  = lane & 3;
    const int rowb = blockIdx.y * BM;
    const int nb   = blockIdx.x * BN;
    const int h0t  = blockIdx.x * 32;

    const uint32_t sb = (uint32_t)__cvta_generic_to_shared(smem);

    // bias preload
    {
        float4* bbuf = (float4*)((char*)smem + BIAS_BYTE_OFF);
        const float4* src = (const float4*)bs;
        for (int i = tid; i < 384; i += NTHREADS) bbuf[i] = src[i];
    }

    float acc[2][6][4];
#pragma unroll
    for (int i = 0; i < 2; i++)
#pragma unroll
        for (int j = 0; j < 6; j++)
#pragma unroll
            for (int q = 0; q < 4; q++) acc[i][j][q] = 0.0f;

    auto issue = [&](int kt) {
        const int s = kt % STAGES;
        const uint32_t sA = sb + (uint32_t)(s * STAGE_BYTES);
        const uint32_t sB = sA + A_BYTES;
        const int chunk = kt >> 2;             // 4 k-tiles per 256-wide chunk
        const int j0 = (kt & 3) * 64;
        const int which = (chunk <= 2) ? 0 : (chunk - 2);
        const __half* abase = g_af + (size_t)which * (TTOK * HD);
        const int shift = (chunk == 1) ? -1 : (chunk == 2) ? 1 : 0;
        const int mode  = (chunk == 1) ? 1 : (chunk == 2) ? 2 : 0;
#pragma unroll
        for (int i = 0; i < 2; i++) {          // A: 1024 16B chunks
            int idx = tid + i * NTHREADS;
            int r  = idx >> 3;
            int f4 = idx & 7;
            int t  = rowb + r;
            int l  = t & LMASK;
            bool valid = (mode == 0) || (mode == 1 ? (l != 0) : (l != LMASK));
            const __half* src = valid ? (abase + (size_t)(t + shift) * HD + j0 + f4 * 8)
                                      : abase;   // src-size=0 -> zero fill
            cp16(sA + (uint32_t)(r * ROWB + f4 * 16), src, valid ? 16u : 0u);
        }
        const __half* wbase = g_Wh + (size_t)nb * KD + kt * BK;
#pragma unroll
        for (int i = 0; i < 3; i++) {          // B: 1536 16B chunks
            int idx = tid + i * NTHREADS;
            int r  = idx >> 3;
            int f4 = idx & 7;
            cp16f(sB + (uint32_t)(r * ROWB + f4 * 16),
                  wbase + (size_t)r * KD + f4 * 8);
        }
        asm volatile("cp.async.commit_group;\n");
    };

    issue(0);
    issue(1);

    // ldmatrix lane addressing
    const int lj = lane >> 3;
    const int ls = lane & 7;
    const uint32_t a_lane_off =
        (uint32_t)((wr * 32 + (lj & 1) * 8 + ls) * ROWB + (lj >> 1) * 16);
    const uint32_t b_lane_off =
        (uint32_t)((wc * 48 + (lj & 1) * 8 + ls) * ROWB + (lj >> 1) * 16);

#pragma unroll 1
    for (int kt = 0; kt < KITERS; ++kt) {
        asm volatile("cp.async.wait_group 1;\n");
        __syncthreads();
        if (kt + 2 < KITERS) issue(kt + 2);
        else asm volatile("cp.async.commit_group;\n");

        if (kt == KITERS - 4 && tid < 384) {
            // L2-prefetch the c_t lines the epilogue will read (clamped)
            int r = tid & 127;
            int sgn = (tid >> 7) - 1;          // -1, 0, 1
            int t = rowb + r + sgn;
            t = (t < 0) ? 0 : (t >= TTOK ? TTOK - 1 : t);
            asm volatile("prefetch.global.L2 [%0];"
                         :: "l"(c_t + (size_t)t * HD + h0t));
        }

        const int st = kt % STAGES;
        const uint32_t aA = sb + (uint32_t)(st * STAGE_BYTES) + a_lane_off;
        const uint32_t aB = sb + (uint32_t)(st * STAGE_BYTES) + A_BYTES + b_lane_off;

        uint32_t a[2][2][4], b[2][6][2];   // [buf][tile][regs]
#pragma unroll
        for (int mt = 0; mt < 2; mt++)
            ldsm4(a[0][mt][0], a[0][mt][1], a[0][mt][2], a[0][mt][3],
                  aA + (uint32_t)(mt * 16 * ROWB));
#pragma unroll
        for (int bt = 0; bt < 3; bt++) {
            uint32_t r0, r1, r2, r3;
            ldsm4(r0, r1, r2, r3, aB + (uint32_t)(bt * 16 * ROWB));
            b[0][2 * bt][0] = r0; b[0][2 * bt + 1][0] = r1;
            b[0][2 * bt][1] = r2; b[0][2 * bt + 1][1] = r3;
        }

#pragma unroll
        for (int ks = 0; ks < 4; ++ks) {       // four k16 steps per BK=64
            const int cur = ks & 1;
            const int nxt = cur ^ 1;
            if (ks < 3) {
                const uint32_t ko = (uint32_t)((ks + 1) * 32);
#pragma unroll
                for (int mt = 0; mt < 2; mt++)
                    ldsm4(a[nxt][mt][0], a[nxt][mt][1], a[nxt][mt][2], a[nxt][mt][3],
                          aA + (uint32_t)(mt * 16 * ROWB) + ko);
#pragma unroll
                for (int bt = 0; bt < 3; bt++) {
                    uint32_t r0, r1, r2, r3;
                    ldsm4(r0, r1, r2, r3, aB + (uint32_t)(bt * 16 * ROWB) + ko);
                    b[nxt][2 * bt][0] = r0; b[nxt][2 * bt + 1][0] = r1;
                    b[nxt][2 * bt][1] = r2; b[nxt][2 * bt + 1][1] = r3;
                }
            }
#pragma unroll
            for (int mt = 0; mt < 2; mt++)
#pragma unroll
                for (int nt = 0; nt < 6; nt++) {
                    asm volatile(
                        "mma.sync.aligned.m16n8k16.row.col.f32.f16.f16.f32 "
                        "{%0,%1,%2,%3}, {%4,%5,%6,%7}, {%8,%9}, {%0,%1,%2,%3};\n"
                        : "+f"(acc[mt][nt][0]), "+f"(acc[mt][nt][1]),
                          "+f"(acc[mt][nt][2]), "+f"(acc[mt][nt][3])
                        : "r"(a[cur][mt][0]), "r"(a[cur][mt][1]),
                          "r"(a[cur][mt][2]), "r"(a[cur][mt][3]),
                          "r"(b[cur][nt][0]), "r"(b[cur][nt][1]));
                }
        }
    }

    asm volatile("cp.async.wait_group 0;\n");
    __syncthreads();

    // stage accumulators: gates[r][h_local*6+g] (128 rows x 192 cols)
    float* gs = smem;
#pragma unroll
    for (int mt = 0; mt < 2; mt++) {
#pragma unroll
        for (int nt = 0; nt < 6; nt++) {
            int r = wr * 32 + mt * 16 + gID;
            int c = wc * 48 + nt * 8 + t4 * 2;
            *(float2*)(gs + r       * GSTRIDE + c) = make_float2(acc[mt][nt][0], acc[mt][nt][1]);
            *(float2*)(gs + (r + 8) * GSTRIDE + c) = make_float2(acc[mt][nt][2], acc[mt][nt][3]);
        }
    }
    __syncthreads();

    // fused epilogue: each warp handles 8 token rows x 32 h (lane = h)
    const float* bb = (const float*)((char*)smem + BIAS_BYTE_OFF);
    const int h = h0t + lane;
#pragma unroll 1
    for (int it = 0; it < 8; it++) {
        const int r = warp * 8 + it;
        const int t = rowb + r;
        const int l = t & LMASK;
        const float* gp = gs + r * GSTRIDE + lane * 6;
        float I  = fsig(gp[0] + bb[h]);
        float O  = fsig(gp[1] + bb[256  + h]);
        float F  = fsig(gp[2] + bb[512  + h]);
        float Lg = fsig(gp[3] + bb[768  + h]);
        float R  = fsig(gp[4] + bb[1024 + h]);
        float U  = tanh_fast(gp[5] + bb[1280 + h]);
        float cm = c_t[(size_t)t * HD + h];
        float cl = (l != 0)     ? c_t[(size_t)(t - 1) * HD + h] : 0.0f;
        float cr = (l != LMASK) ? c_t[(size_t)(t + 1) * HD + h] : 0.0f;
        float ei = __expf(I), ef = __expf(F), el = __expf(Lg), er = __expf(R);
        float inv = 1.0f / (ei + ef + el + er);
        float c = (ef * cm + el * cl + er * cr + ei * U) * inv;
        float hn = O * tanh_fast(c);
        out[(size_t)t * HD + h] = hn;
        out[OUT_HALF + (size_t)t * HD + h] = c;
    }
}

// ---------------- launch ----------------
extern "C" void kernel_launch(void* const* d_in, const int* in_sizes, int n_in,
                              void* d_out, int out_size) {
    (void)in_sizes; (void)n_in; (void)out_size;
    const float* h_t      = (const float*)d_in[0];
    const float* x        = (const float*)d_in[1];
    const float* h_slot   = (const float*)d_in[2];
    const float* h_intent = (const float*)d_in[3];
    const float* c_t      = (const float*)d_in[4];
    const float* Ws       = (const float*)d_in[5];
    const float* bs       = (const float*)d_in[6];
    float* out = (float*)d_out;

    cudaFuncSetAttribute(slstm_kernel, cudaFuncAttributeMaxDynamicSharedMemorySize,
                         SMEM_TOTAL);

    prep_kernel<<<A_BLOCKS + W_BLOCKS, 256>>>(Ws, h_t, x, h_slot, h_intent);
    slstm_kernel<<<dim3(NT, MT), NTHREADS, SMEM_TOTAL>>>(c_t, bs, out);
}

// round 13
// speedup vs baseline: 1.1903x; 1.0102x over previous
#include <cuda_runtime.h>
#include <cuda_fp16.h>
#include <cstdint>

// ---------------- problem constants ----------------
#define TTOK   65536           // B*L
#define HD     256
#define KD     1536            // 6*H
#define ND     1536            // 6 gates * H, n = h*6+g
#define LMASK  2047
#define OUT_HALF 16777216ull   // TTOK*HD

// ---------------- tiling ----------------
#define BM      128
#define BN      192
#define NT      8              // ND / BN
#define MT      512            // TTOK / BM
#define BK      64             // fp16 k elems per tile (128 B)
#define KITERS  24             // KD / BK
#define NTHREADS 512
#define ROWB    144            // bytes per smem row (64 fp16 + 16 pad)
#define A_BYTES (130*ROWB)     // 18720 (130-row A tile: slots 0..129)
#define B_BYTES (BN*ROWB)      // 27648
#define B_RING_OFF (3*A_BYTES)             // 56160
#define GSTRIDE 194            // gates staging row stride (floats)
#define BIAS_BYTE_OFF (B_RING_OFF + 3*B_BYTES)  // 139104
#define SMEM_TOTAL (BIAS_BYTE_OFF + 6144)       // 145248 bytes

__device__ __half g_Wh[(size_t)ND * KD];          // [n][k], n-major fp16
__device__ __half g_af[4ull * TTOK * HD];         // fp16: h_t, x, h_slot, h_intent

__device__ __forceinline__ uint32_t h2_to_u32(__half2 v) {
    union { __half2 h; uint32_t u; } cvt;
    cvt.h = v;
    return cvt.u;
}

// atile id per k-iteration: kt<12 -> j0 tile of h_t (0..3), kt>=12 -> 4..15
__device__ __host__ __forceinline__ int atile_of(int kt) {
    return (kt < 12) ? (kt / 3) : (4 + (kt - 12));
}

// ---------------- merged prep ----------------
#define A_BLOCKS 32768         // 4 tensors * 8192
#define W_BLOCKS 288           // 6 g * 24 ktiles * 2 hhalves

__global__ __launch_bounds__(256) void prep_kernel(
    const float* __restrict__ Ws,
    const float* __restrict__ h_t, const float* __restrict__ x,
    const float* __restrict__ h_slot, const float* __restrict__ h_intent)
{
    __shared__ float s[64][133];
    const int bid = blockIdx.x;
    const int tid = threadIdx.x;
    if (bid < A_BLOCKS) {
        const int which = bid >> 13;           // 0..3
        const float* src = (which == 0) ? h_t : (which == 1) ? x
                         : (which == 2) ? h_slot : h_intent;
        __half* dst = g_af + (size_t)which * (TTOK * HD);
        const size_t i = (((size_t)(bid & 8191)) * 256 + tid) * 8;
        float4 v0 = *(const float4*)(src + i);
        float4 v1 = *(const float4*)(src + i + 4);
        uint4 pk = make_uint4(h2_to_u32(__floats2half2_rn(v0.x, v0.y)),
                              h2_to_u32(__floats2half2_rn(v0.z, v0.w)),
                              h2_to_u32(__floats2half2_rn(v1.x, v1.y)),
                              h2_to_u32(__floats2half2_rn(v1.z, v1.w)));
        *(uint4*)(dst + i) = pk;
    } else {
        const int bw = bid - A_BLOCKS;         // 0..287
        const int g  = bw / 48;
        const int rem = bw - g * 48;
        const int kt = rem >> 1;
        const int k0 = kt * 64;
        const int h0 = (rem & 1) * 128;
#pragma unroll
        for (int p = 0; p < 8; p++) {
            int i  = tid + p * 256;
            int k  = i >> 5;
            int f4 = i & 31;
            float4 v = *(const float4*)(Ws + ((size_t)g * KD + k0 + k) * HD + h0 + f4 * 4);
            s[k][f4 * 4 + 0] = v.x;
            s[k][f4 * 4 + 1] = v.y;
            s[k][f4 * 4 + 2] = v.z;
            s[k][f4 * 4 + 3] = v.w;
        }
        __syncthreads();
        const int lane = tid & 31;
        const int wrow = tid >> 5;
#pragma unroll
        for (int p = 0; p < 16; p++) {
            int h = wrow + p * 8;
            int n = (h0 + h) * 6 + g;
            __half2 v = __floats2half2_rn(s[2 * lane][h], s[2 * lane + 1][h]);
            *(__half2*)(g_Wh + (size_t)n * KD + k0 + 2 * lane) = v;
        }
    }
}

// ---------------- helpers ----------------
__device__ __forceinline__ void cp16(uint32_t dst, const void* src, uint32_t sz) {
    asm volatile("cp.async.ca.shared.global [%0], [%1], 16, %2;\n"
                 :: "r"(dst), "l"(src), "r"(sz));
}
__device__ __forceinline__ void cp16f(uint32_t dst, const void* src) {
    asm volatile("cp.async.ca.shared.global [%0], [%1], 16;\n"
                 :: "r"(dst), "l"(src));
}
__device__ __forceinline__ void ldsm4(uint32_t& r0, uint32_t& r1, uint32_t& r2,
                                      uint32_t& r3, uint32_t addr) {
    asm volatile("ldmatrix.sync.aligned.m8n8.x4.shared.b16 {%0,%1,%2,%3}, [%4];"
                 : "=r"(r0), "=r"(r1), "=r"(r2), "=r"(r3) : "r"(addr));
}
__device__ __forceinline__ float tanh_fast(float x) {
    float y;
    asm("tanh.approx.f32 %0, %1;" : "=f"(y) : "f"(x));
    return y;
}
__device__ __forceinline__ float fsig(float v)  { return 0.5f * tanh_fast(0.5f * v) + 0.5f; }

__global__ __launch_bounds__(NTHREADS, 1) void slstm_kernel(
    const float* __restrict__ c_t, const float* __restrict__ bs,
    float* __restrict__ out)
{
    extern __shared__ float smem[];
    const int tid  = threadIdx.x;
    const int warp = tid >> 5;
    const int lane = tid & 31;
    const int wr = warp & 3;           // 4 warp rows (M, 32 each)
    const int wc = warp >> 2;          // 4 warp cols (N, 48 each)
    const int gID = lane >> 2;
    const int t4  = lane & 3;
    const int rowb = blockIdx.y * BM;
    const int nb   = blockIdx.x * BN;
    const int h0t  = blockIdx.x * 32;

    const uint32_t sb = (uint32_t)__cvta_generic_to_shared(smem);

    // bias preload
    {
        float4* bbuf = (float4*)((char*)smem + BIAS_BYTE_OFF);
        const float4* src = (const float4*)bs;
        for (int i = tid; i < 384; i += NTHREADS) bbuf[i] = src[i];
    }

    float acc[2][6][4];
#pragma unroll
    for (int i = 0; i < 2; i++)
#pragma unroll
        for (int j = 0; j < 6; j++)
#pragma unroll
            for (int q = 0; q < 4; q++) acc[i][j][q] = 0.0f;

    // ---- A tile load (ring of 3) ----
    auto issueA = [&](int atile) {
        const uint32_t sA = sb + (uint32_t)((atile % 3) * A_BYTES);
        if (atile < 4) {
            // h_t tile: 130 rows (slots 0..129 = tokens rowb-1 .. rowb+128)
            const int j0 = atile * 64;
            const __half* hb = g_af;       // which = 0
#pragma unroll
            for (int i = 0; i < 3; i++) {
                int idx = tid + i * NTHREADS;
                if (idx < 1040) {
                    int r  = idx >> 3;     // slot 0..129
                    int f4 = idx & 7;
                    bool valid = true;
                    if (r == 0)        valid = (rowb & LMASK) != 0;
                    else if (r == 129) valid = ((rowb + BM) & LMASK) != 0;
                    const __half* src = valid
                        ? (hb + (size_t)(rowb + r - 1) * HD + j0 + f4 * 8)
                        : hb;              // src-size=0 -> zero fill
                    cp16(sA + (uint32_t)(r * ROWB + f4 * 16), src, valid ? 16u : 0u);
                }
            }
        } else {
            // x / h_slot / h_intent tile: 128 rows at slots 1..128
            const int w = atile - 4;       // 0..11
            const int which = 1 + (w >> 2);
            const int j0 = (w & 3) * 64;
            const __half* abase = g_af + (size_t)which * (TTOK * HD);
#pragma unroll
            for (int i = 0; i < 2; i++) {
                int idx = tid + i * NTHREADS;
                int r  = idx >> 3;
                int f4 = idx & 7;
                cp16f(sA + (uint32_t)((r + 1) * ROWB + f4 * 16),
                      abase + (size_t)(rowb + r) * HD + j0 + f4 * 8);
            }
        }
    };

    // ---- B tile load (ring of 3) ----
    auto issueB = [&](int kt) {
        const uint32_t sB = sb + B_RING_OFF + (uint32_t)((kt % 3) * B_BYTES);
        int chunk, j0;
        if (kt < 12) { chunk = kt % 3;            j0 = (kt / 3) * 64; }
        else         { chunk = 3 + ((kt - 12) >> 2); j0 = ((kt - 12) & 3) * 64; }
        const __half* wbase = g_Wh + (size_t)nb * KD + chunk * 256 + j0;
#pragma unroll
        for (int i = 0; i < 3; i++) {
            int idx = tid + i * NTHREADS;
            int r  = idx >> 3;
            int f4 = idx & 7;
            cp16f(sB + (uint32_t)(r * ROWB + f4 * 16),
                  wbase + (size_t)r * KD + f4 * 8);
        }
    };

    // prologue: groups for kt=0 and kt=1
    issueA(0);
    issueB(0);
    asm volatile("cp.async.commit_group;\n");
    issueB(1);                     // atile(1)==atile(0): no A
    asm volatile("cp.async.commit_group;\n");

    // ldmatrix lane addressing (relative to tile base slot)
    const int lj = lane >> 3;
    const int ls = lane & 7;
    const uint32_t a_lane_off =
        (uint32_t)((wr * 32 + (lj & 1) * 8 + ls) * ROWB + (lj >> 1) * 16);
    const uint32_t b_lane_off =
        (uint32_t)((wc * 48 + (lj & 1) * 8 + ls) * ROWB + (lj >> 1) * 16);

#pragma unroll 1
    for (int kt = 0; kt < KITERS; ++kt) {
        asm volatile("cp.async.wait_group 1;\n");
        __syncthreads();
        if (kt + 2 < KITERS) {
            if (atile_of(kt + 2) != atile_of(kt + 1)) issueA(atile_of(kt + 2));
            issueB(kt + 2);
            asm volatile("cp.async.commit_group;\n");
        } else {
            asm volatile("cp.async.commit_group;\n");
        }

        if (kt == KITERS - 4 && tid < 384) {
            int r = tid & 127;
            int sgn = (tid >> 7) - 1;          // -1, 0, 1
            int t = rowb + r + sgn;
            t = (t < 0) ? 0 : (t >= TTOK ? TTOK - 1 : t);
            asm volatile("prefetch.global.L2 [%0];"
                         :: "l"(c_t + (size_t)t * HD + h0t));
        }

        // base slot within the A tile: mid->1, left->0, right->2, non-h->1
        int base_slot = 1;
        if (kt < 12) {
            int chunk = kt % 3;
            base_slot = (chunk == 0) ? 1 : (chunk == 1 ? 0 : 2);
        }
        const uint32_t aA = sb + (uint32_t)((atile_of(kt) % 3) * A_BYTES)
                          + (uint32_t)(base_slot * ROWB) + a_lane_off;
        const uint32_t aB = sb + B_RING_OFF + (uint32_t)((kt % 3) * B_BYTES) + b_lane_off;

        uint32_t a[2][2][4], b[2][6][2];   // [buf][tile][regs]
#pragma unroll
        for (int mt = 0; mt < 2; mt++)
            ldsm4(a[0][mt][0], a[0][mt][1], a[0][mt][2], a[0][mt][3],
                  aA + (uint32_t)(mt * 16 * ROWB));
#pragma unroll
        for (int bt = 0; bt < 3; bt++) {
            uint32_t r0, r1, r2, r3;
            ldsm4(r0, r1, r2, r3, aB + (uint32_t)(bt * 16 * ROWB));
            b[0][2 * bt][0] = r0; b[0][2 * bt + 1][0] = r1;
            b[0][2 * bt][1] = r2; b[0][2 * bt + 1][1] = r3;
        }

#pragma unroll
        for (int ks = 0; ks < 4; ++ks) {       // four k16 steps per BK=64
            const int cur = ks & 1;
            const int nxt = cur ^ 1;
            if (ks < 3) {
                const uint32_t ko = (uint32_t)((ks + 1) * 32);
#pragma unroll
                for (int mt = 0; mt < 2; mt++)
                    ldsm4(a[nxt][mt][0], a[nxt][mt][1], a[nxt][mt][2], a[nxt][mt][3],
                          aA + (uint32_t)(mt * 16 * ROWB) + ko);
#pragma unroll
                for (int bt = 0; bt < 3; bt++) {
                    uint32_t r0, r1, r2, r3;
                    ldsm4(r0, r1, r2, r3, aB + (uint32_t)(bt * 16 * ROWB) + ko);
                    b[nxt][2 * bt][0] = r0; b[nxt][2 * bt + 1][0] = r1;
                    b[nxt][2 * bt][1] = r2; b[nxt][2 * bt + 1][1] = r3;
                }
            }
#pragma unroll
            for (int mt = 0; mt < 2; mt++)
#pragma unroll
                for (int nt = 0; nt < 6; nt++) {
                    asm volatile(
                        "mma.sync.aligned.m16n8k16.row.col.f32.f16.f16.f32 "
                        "{%0,%1,%2,%3}, {%4,%5,%6,%7}, {%8,%9}, {%0,%1,%2,%3};\n"
                        : "+f"(acc[mt][nt][0]), "+f"(acc[mt][nt][1]),
                          "+f"(acc[mt][nt][2]), "+f"(acc[mt][nt][3])
                        : "r"(a[cur][mt][0]), "r"(a[cur][mt][1]),
                          "r"(a[cur][mt][2]), "r"(a[cur][mt][3]),
                          "r"(b[cur][nt][0]), "r"(b[cur][nt][1]));
                }
        }
    }

    asm volatile("cp.async.wait_group 0;\n");
    __syncthreads();

    // stage accumulators: gates[r][h_local*6+g] (128 rows x 192 cols)
    float* gs = smem;
#pragma unroll
    for (int mt = 0; mt < 2; mt++) {
#pragma unroll
        for (int nt = 0; nt < 6; nt++) {
            int r = wr * 32 + mt * 16 + gID;
            int c = wc * 48 + nt * 8 + t4 * 2;
            *(float2*)(gs + r       * GSTRIDE + c) = make_float2(acc[mt][nt][0], acc[mt][nt][1]);
            *(float2*)(gs + (r + 8) * GSTRIDE + c) = make_float2(acc[mt][nt][2], acc[mt][nt][3]);
        }
    }
    __syncthreads();

    // fused epilogue: each warp handles 8 token rows x 32 h (lane = h)
    const float* bb = (const float*)((char*)smem + BIAS_BYTE_OFF);
    const int h = h0t + lane;
#pragma unroll 1
    for (int it = 0; it < 8; it++) {
        const int r = warp * 8 + it;
        const int t = rowb + r;
        const int l = t & LMASK;
        const float* gp = gs + r * GSTRIDE + lane * 6;
        float I  = fsig(gp[0] + bb[h]);
        float O  = fsig(gp[1] + bb[256  + h]);
        float F  = fsig(gp[2] + bb[512  + h]);
        float Lg = fsig(gp[3] + bb[768  + h]);
        float R  = fsig(gp[4] + bb[1024 + h]);
        float U  = tanh_fast(gp[5] + bb[1280 + h]);
        float cm = c_t[(size_t)t * HD + h];
        float cl = (l != 0)     ? c_t[(size_t)(t - 1) * HD + h] : 0.0f;
        float cr = (l != LMASK) ? c_t[(size_t)(t + 1) * HD + h] : 0.0f;
        float ei = __expf(I), ef = __expf(F), el = __expf(Lg), er = __expf(R);
        float inv = 1.0f / (ei + ef + el + er);
        float c = (ef * cm + el * cl + er * cr + ei * U) * inv;
        float hn = O * tanh_fast(c);
        out[(size_t)t * HD + h] = hn;
        out[OUT_HALF + (size_t)t * HD + h] = c;
    }
}

// ---------------- launch ----------------
extern "C" void kernel_launch(void* const* d_in, const int* in_sizes, int n_in,
                              void* d_out, int out_size) {
    (void)in_sizes; (void)n_in; (void)out_size;
    const float* h_t      = (const float*)d_in[0];
    const float* x        = (const float*)d_in[1];
    const float* h_slot   = (const float*)d_in[2];
    const float* h_intent = (const float*)d_in[3];
    const float* c_t      = (const float*)d_in[4];
    const float* Ws       = (const float*)d_in[5];
    const float* bs       = (const float*)d_in[6];
    float* out = (float*)d_out;

    cudaFuncSetAttribute(slstm_kernel, cudaFuncAttributeMaxDynamicSharedMemorySize,
                         SMEM_TOTAL);

    prep_kernel<<<A_BLOCKS + W_BLOCKS, 256>>>(Ws, h_t, x, h_slot, h_intent);
    slstm_kernel<<<dim3(NT, MT), NTHREADS, SMEM_TOTAL>>>(c_t, bs, out);
}

// round 14
// speedup vs baseline: 1.1993x; 1.0075x over previous
#include <cuda_runtime.h>
#include <cuda_fp16.h>
#include <cstdint>

// ---------------- problem constants ----------------
#define TTOK   65536           // B*L
#define HD     256
#define KD     1536            // 6*H
#define ND     1536            // 6 gates * H, n = h*6+g
#define LMASK  2047
#define OUT_HALF 16777216ull   // TTOK*HD

// ---------------- tiling ----------------
#define BM      128
#define BN      192
#define NT      8              // ND / BN
#define MT      512            // TTOK / BM
#define BK      64             // fp16 k elems per tile (128 B)
#define KITERS  24             // KD / BK
#define NTHREADS 512
#define ROWB    144            // bytes per smem row (64 fp16 + 16 pad)
#define A_BYTES (130*ROWB)     // 18720 (130-row A tile: slots 0..129)
#define B_BYTES (BN*ROWB)      // 27648
#define B_RING_OFF (3*A_BYTES)             // 56160
#define GSTRIDE 194            // gates staging row stride (floats)
#define BIAS_BYTE_OFF (B_RING_OFF + 3*B_BYTES)  // 139104
#define SMEM_TOTAL (BIAS_BYTE_OFF + 6144)       // 145248 bytes

__device__ __half g_Wh[(size_t)ND * KD];          // [n][k], n-major fp16
__device__ __half g_af[4ull * TTOK * HD];         // fp16: h_t, x, h_slot, h_intent

__device__ __forceinline__ uint32_t h2_to_u32(__half2 v) {
    union { __half2 h; uint32_t u; } cvt;
    cvt.h = v;
    return cvt.u;
}

// atile id per k-iteration: kt<12 -> j0 tile of h_t (0..3), kt>=12 -> 4..15
__device__ __host__ __forceinline__ int atile_of(int kt) {
    return (kt < 12) ? (kt / 3) : (4 + (kt - 12));
}

// ---------------- merged prep (512 threads) ----------------
#define A_BLOCKS 8192          // 4 tensors * 2048 (8192 elems per block)
#define W_BLOCKS 288           // 6 g * 24 ktiles * 2 hhalves

__global__ __launch_bounds__(512) void prep_kernel(
    const float* __restrict__ Ws,
    const float* __restrict__ h_t, const float* __restrict__ x,
    const float* __restrict__ h_slot, const float* __restrict__ h_intent)
{
    __shared__ float s[64][133];
    const int bid = blockIdx.x;
    const int tid = threadIdx.x;
    if (bid < A_BLOCKS) {
        const int which = bid >> 11;           // 0..3
        const float* src = (which == 0) ? h_t : (which == 1) ? x
                         : (which == 2) ? h_slot : h_intent;
        __half* dst = g_af + (size_t)which * (TTOK * HD);
        const size_t i = (((size_t)(bid & 2047)) * 512 + tid) * 16;
        float4 v0 = __ldcs((const float4*)(src + i));
        float4 v1 = __ldcs((const float4*)(src + i + 4));
        float4 v2 = __ldcs((const float4*)(src + i + 8));
        float4 v3 = __ldcs((const float4*)(src + i + 12));
        uint4 p0 = make_uint4(h2_to_u32(__floats2half2_rn(v0.x, v0.y)),
                              h2_to_u32(__floats2half2_rn(v0.z, v0.w)),
                              h2_to_u32(__floats2half2_rn(v1.x, v1.y)),
                              h2_to_u32(__floats2half2_rn(v1.z, v1.w)));
        uint4 p1 = make_uint4(h2_to_u32(__floats2half2_rn(v2.x, v2.y)),
                              h2_to_u32(__floats2half2_rn(v2.z, v2.w)),
                              h2_to_u32(__floats2half2_rn(v3.x, v3.y)),
                              h2_to_u32(__floats2half2_rn(v3.z, v3.w)));
        *(uint4*)(dst + i) = p0;
        *(uint4*)(dst + i + 8) = p1;
    } else {
        const int bw = bid - A_BLOCKS;         // 0..287
        const int g  = bw / 48;
        const int rem = bw - g * 48;
        const int kt = rem >> 1;
        const int k0 = kt * 64;
        const int h0 = (rem & 1) * 128;
#pragma unroll
        for (int p = 0; p < 4; p++) {
            int i  = tid + p * 512;            // 2048 float4 loads
            int k  = i >> 5;
            int f4 = i & 31;
            float4 v = __ldcs((const float4*)(Ws + ((size_t)g * KD + k0 + k) * HD + h0 + f4 * 4));
            s[k][f4 * 4 + 0] = v.x;
            s[k][f4 * 4 + 1] = v.y;
            s[k][f4 * 4 + 2] = v.z;
            s[k][f4 * 4 + 3] = v.w;
        }
        __syncthreads();
        const int lane = tid & 31;
        const int wrow = tid >> 5;             // 0..15
#pragma unroll
        for (int p = 0; p < 8; p++) {
            int h = wrow + p * 16;
            int n = (h0 + h) * 6 + g;
            __half2 v = __floats2half2_rn(s[2 * lane][h], s[2 * lane + 1][h]);
            *(__half2*)(g_Wh + (size_t)n * KD + k0 + 2 * lane) = v;
        }
    }
}

// ---------------- helpers ----------------
__device__ __forceinline__ void cp16(uint32_t dst, const void* src, uint32_t sz) {
    asm volatile("cp.async.ca.shared.global [%0], [%1], 16, %2;\n"
                 :: "r"(dst), "l"(src), "r"(sz));
}
__device__ __forceinline__ void cp16f(uint32_t dst, const void* src) {
    asm volatile("cp.async.ca.shared.global [%0], [%1], 16;\n"
                 :: "r"(dst), "l"(src));
}
__device__ __forceinline__ void ldsm4(uint32_t& r0, uint32_t& r1, uint32_t& r2,
                                      uint32_t& r3, uint32_t addr) {
    asm volatile("ldmatrix.sync.aligned.m8n8.x4.shared.b16 {%0,%1,%2,%3}, [%4];"
                 : "=r"(r0), "=r"(r1), "=r"(r2), "=r"(r3) : "r"(addr));
}
__device__ __forceinline__ float tanh_fast(float x) {
    float y;
    asm("tanh.approx.f32 %0, %1;" : "=f"(y) : "f"(x));
    return y;
}
__device__ __forceinline__ float fsig(float v)  { return 0.5f * tanh_fast(0.5f * v) + 0.5f; }

__global__ __launch_bounds__(NTHREADS, 1) void slstm_kernel(
    const float* __restrict__ c_t, const float* __restrict__ bs,
    float* __restrict__ out)
{
    extern __shared__ float smem[];
    const int tid  = threadIdx.x;
    const int warp = tid >> 5;
    const int lane = tid & 31;
    const int wr = warp & 3;           // 4 warp rows (M, 32 each)
    const int wc = warp >> 2;          // 4 warp cols (N, 48 each)
    const int gID = lane >> 2;
    const int t4  = lane & 3;
    const int rowb = blockIdx.y * BM;
    const int nb   = blockIdx.x * BN;
    const int h0t  = blockIdx.x * 32;

    const uint32_t sb = (uint32_t)__cvta_generic_to_shared(smem);

    // bias preload
    {
        float4* bbuf = (float4*)((char*)smem + BIAS_BYTE_OFF);
        const float4* src = (const float4*)bs;
        for (int i = tid; i < 384; i += NTHREADS) bbuf[i] = src[i];
    }

    float acc[2][6][4];
#pragma unroll
    for (int i = 0; i < 2; i++)
#pragma unroll
        for (int j = 0; j < 6; j++)
#pragma unroll
            for (int q = 0; q < 4; q++) acc[i][j][q] = 0.0f;

    // ---- A tile load (ring of 3) ----
    auto issueA = [&](int atile) {
        const uint32_t sA = sb + (uint32_t)((atile % 3) * A_BYTES);
        if (atile < 4) {
            // h_t tile: 130 rows (slots 0..129 = tokens rowb-1 .. rowb+128)
            const int j0 = atile * 64;
            const __half* hb = g_af;       // which = 0
#pragma unroll
            for (int i = 0; i < 3; i++) {
                int idx = tid + i * NTHREADS;
                if (idx < 1040) {
                    int r  = idx >> 3;     // slot 0..129
                    int f4 = idx & 7;
                    bool valid = true;
                    if (r == 0)        valid = (rowb & LMASK) != 0;
                    else if (r == 129) valid = ((rowb + BM) & LMASK) != 0;
                    const __half* src = valid
                        ? (hb + (size_t)(rowb + r - 1) * HD + j0 + f4 * 8)
                        : hb;              // src-size=0 -> zero fill
                    cp16(sA + (uint32_t)(r * ROWB + f4 * 16), src, valid ? 16u : 0u);
                }
            }
        } else {
            // x / h_slot / h_intent tile: 128 rows at slots 1..128
            const int w = atile - 4;       // 0..11
            const int which = 1 + (w >> 2);
            const int j0 = (w & 3) * 64;
            const __half* abase = g_af + (size_t)which * (TTOK * HD);
#pragma unroll
            for (int i = 0; i < 2; i++) {
                int idx = tid + i * NTHREADS;
                int r  = idx >> 3;
                int f4 = idx & 7;
                cp16f(sA + (uint32_t)((r + 1) * ROWB + f4 * 16),
                      abase + (size_t)(rowb + r) * HD + j0 + f4 * 8);
            }
        }
    };

    // ---- B tile load (ring of 3) ----
    auto issueB = [&](int kt) {
        const uint32_t sB = sb + B_RING_OFF + (uint32_t)((kt % 3) * B_BYTES);
        int chunk, j0;
        if (kt < 12) { chunk = kt % 3;            j0 = (kt / 3) * 64; }
        else         { chunk = 3 + ((kt - 12) >> 2); j0 = ((kt - 12) & 3) * 64; }
        const __half* wbase = g_Wh + (size_t)nb * KD + chunk * 256 + j0;
#pragma unroll
        for (int i = 0; i < 3; i++) {
            int idx = tid + i * NTHREADS;
            int r  = idx >> 3;
            int f4 = idx & 7;
            cp16f(sB + (uint32_t)(r * ROWB + f4 * 16),
                  wbase + (size_t)r * KD + f4 * 8);
        }
    };

    // prologue: groups for kt=0 and kt=1
    issueA(0);
    issueB(0);
    asm volatile("cp.async.commit_group;\n");
    issueB(1);                     // atile(1)==atile(0): no A
    asm volatile("cp.async.commit_group;\n");

    // ldmatrix lane addressing (relative to tile base slot)
    const int lj = lane >> 3;
    const int ls = lane & 7;
    const uint32_t a_lane_off =
        (uint32_t)((wr * 32 + (lj & 1) * 8 + ls) * ROWB + (lj >> 1) * 16);
    const uint32_t b_lane_off =
        (uint32_t)((wc * 48 + (lj & 1) * 8 + ls) * ROWB + (lj >> 1) * 16);

#pragma unroll 1
    for (int kt = 0; kt < KITERS; ++kt) {
        asm volatile("cp.async.wait_group 1;\n");
        __syncthreads();
        if (kt + 2 < KITERS) {
            if (atile_of(kt + 2) != atile_of(kt + 1)) issueA(atile_of(kt + 2));
            issueB(kt + 2);
            asm volatile("cp.async.commit_group;\n");
        } else {
            asm volatile("cp.async.commit_group;\n");
        }

        if (kt == KITERS - 4 && tid < 384) {
            int r = tid & 127;
            int sgn = (tid >> 7) - 1;          // -1, 0, 1
            int t = rowb + r + sgn;
            t = (t < 0) ? 0 : (t >= TTOK ? TTOK - 1 : t);
            asm volatile("prefetch.global.L2 [%0];"
                         :: "l"(c_t + (size_t)t * HD + h0t));
        }

        // base slot within the A tile: mid->1, left->0, right->2, non-h->1
        int base_slot = 1;
        if (kt < 12) {
            int chunk = kt % 3;
            base_slot = (chunk == 0) ? 1 : (chunk == 1 ? 0 : 2);
        }
        const uint32_t aA = sb + (uint32_t)((atile_of(kt) % 3) * A_BYTES)
                          + (uint32_t)(base_slot * ROWB) + a_lane_off;
        const uint32_t aB = sb + B_RING_OFF + (uint32_t)((kt % 3) * B_BYTES) + b_lane_off;

        uint32_t a[2][2][4], b[2][6][2];   // [buf][tile][regs]
#pragma unroll
        for (int mt = 0; mt < 2; mt++)
            ldsm4(a[0][mt][0], a[0][mt][1], a[0][mt][2], a[0][mt][3],
                  aA + (uint32_t)(mt * 16 * ROWB));
#pragma unroll
        for (int bt = 0; bt < 3; bt++) {
            uint32_t r0, r1, r2, r3;
            ldsm4(r0, r1, r2, r3, aB + (uint32_t)(bt * 16 * ROWB));
            b[0][2 * bt][0] = r0; b[0][2 * bt + 1][0] = r1;
            b[0][2 * bt][1] = r2; b[0][2 * bt + 1][1] = r3;
        }

#pragma unroll
        for (int ks = 0; ks < 4; ++ks) {       // four k16 steps per BK=64
            const int cur = ks & 1;
            const int nxt = cur ^ 1;
            if (ks < 3) {
                const uint32_t ko = (uint32_t)((ks + 1) * 32);
#pragma unroll
                for (int mt = 0; mt < 2; mt++)
                    ldsm4(a[nxt][mt][0], a[nxt][mt][1], a[nxt][mt][2], a[nxt][mt][3],
                          aA + (uint32_t)(mt * 16 * ROWB) + ko);
#pragma unroll
                for (int bt = 0; bt < 3; bt++) {
                    uint32_t r0, r1, r2, r3;
                    ldsm4(r0, r1, r2, r3, aB + (uint32_t)(bt * 16 * ROWB) + ko);
                    b[nxt][2 * bt][0] = r0; b[nxt][2 * bt + 1][0] = r1;
                    b[nxt][2 * bt][1] = r2; b[nxt][2 * bt + 1][1] = r3;
                }
            }
#pragma unroll
            for (int mt = 0; mt < 2; mt++)
#pragma unroll
                for (int nt = 0; nt < 6; nt++) {
                    asm volatile(
                        "mma.sync.aligned.m16n8k16.row.col.f32.f16.f16.f32 "
                        "{%0,%1,%2,%3}, {%4,%5,%6,%7}, {%8,%9}, {%0,%1,%2,%3};\n"
                        : "+f"(acc[mt][nt][0]), "+f"(acc[mt][nt][1]),
                          "+f"(acc[mt][nt][2]), "+f"(acc[mt][nt][3])
                        : "r"(a[cur][mt][0]), "r"(a[cur][mt][1]),
                          "r"(a[cur][mt][2]), "r"(a[cur][mt][3]),
                          "r"(b[cur][nt][0]), "r"(b[cur][nt][1]));
                }
        }
    }

    asm volatile("cp.async.wait_group 0;\n");
    __syncthreads();

    // stage accumulators: gates[r][h_local*6+g] (128 rows x 192 cols)
    float* gs = smem;
#pragma unroll
    for (int mt = 0; mt < 2; mt++) {
#pragma unroll
        for (int nt = 0; nt < 6; nt++) {
            int r = wr * 32 + mt * 16 + gID;
            int c = wc * 48 + nt * 8 + t4 * 2;
            *(float2*)(gs + r       * GSTRIDE + c) = make_float2(acc[mt][nt][0], acc[mt][nt][1]);
            *(float2*)(gs + (r + 8) * GSTRIDE + c) = make_float2(acc[mt][nt][2], acc[mt][nt][3]);
        }
    }
    __syncthreads();

    // fused epilogue: each warp handles 8 token rows x 32 h (lane = h)
    const float* bb = (const float*)((char*)smem + BIAS_BYTE_OFF);
    const int h = h0t + lane;
#pragma unroll 1
    for (int it = 0; it < 8; it++) {
        const int r = warp * 8 + it;
        const int t = rowb + r;
        const int l = t & LMASK;
        const float* gp = gs + r * GSTRIDE + lane * 6;
        float I  = fsig(gp[0] + bb[h]);
        float O  = fsig(gp[1] + bb[256  + h]);
        float F  = fsig(gp[2] + bb[512  + h]);
        float Lg = fsig(gp[3] + bb[768  + h]);
        float R  = fsig(gp[4] + bb[1024 + h]);
        float U  = tanh_fast(gp[5] + bb[1280 + h]);
        float cm = c_t[(size_t)t * HD + h];
        float cl = (l != 0)     ? c_t[(size_t)(t - 1) * HD + h] : 0.0f;
        float cr = (l != LMASK) ? c_t[(size_t)(t + 1) * HD + h] : 0.0f;
        float ei = __expf(I), ef = __expf(F), el = __expf(Lg), er = __expf(R);
        float inv = 1.0f / (ei + ef + el + er);
        float c = (ef * cm + el * cl + er * cr + ei * U) * inv;
        float hn = O * tanh_fast(c);
        out[(size_t)t * HD + h] = hn;
        out[OUT_HALF + (size_t)t * HD + h] = c;
    }
}

// ---------------- launch ----------------
extern "C" void kernel_launch(void* const* d_in, const int* in_sizes, int n_in,
                              void* d_out, int out_size) {
    (void)in_sizes; (void)n_in; (void)out_size;
    const float* h_t      = (const float*)d_in[0];
    const float* x        = (const float*)d_in[1];
    const float* h_slot   = (const float*)d_in[2];
    const float* h_intent = (const float*)d_in[3];
    const float* c_t      = (const float*)d_in[4];
    const float* Ws       = (const float*)d_in[5];
    const float* bs       = (const float*)d_in[6];
    float* out = (float*)d_out;

    cudaFuncSetAttribute(slstm_kernel, cudaFuncAttributeMaxDynamicSharedMemorySize,
                         SMEM_TOTAL);

    prep_kernel<<<A_BLOCKS + W_BLOCKS, 512>>>(Ws, h_t, x, h_slot, h_intent);
    slstm_kernel<<<dim3(NT, MT), NTHREADS, SMEM_TOTAL>>>(c_t, bs, out);
}

// round 16
// speedup vs baseline: 1.2214x; 1.0185x over previous
#include <cuda_runtime.h>
#include <cuda_fp16.h>
#include <cstdint>

// ---------------- problem constants ----------------
#define TTOK   65536           // B*L
#define HD     256
#define KD     1536            // 6*H
#define ND     1536            // 6 gates * H, n = h*6+g
#define LMASK  2047
#define OUT_HALF 16777216ull   // TTOK*HD

// ---------------- tiling ----------------
#define BM      128
#define BN      192
#define NT      8              // ND / BN
#define MT      512            // TTOK / BM
#define BK      64             // fp16 k elems per tile (128 B)
#define KITERS  24             // KD / BK
#define NTHREADS 512
#define ROWB    144            // bytes per smem row (64 fp16 + 16 pad)
#define A_BYTES (130*ROWB)     // 18720 (130-row A tile: slots 0..129)
#define B_BYTES (BN*ROWB)      // 27648
#define B_RING_OFF (3*A_BYTES)             // 56160
#define GS2     260            // gates staging row stride (floats), 16B-aligned rows
#define BIAS_BYTE_OFF (B_RING_OFF + 3*B_BYTES)  // 139104
#define SMEM_TOTAL (BIAS_BYTE_OFF + 6144)       // 145248 bytes

__device__ __half g_Wh[(size_t)ND * KD];          // [n][k], n-major fp16
__device__ __half g_af[4ull * TTOK * HD];         // fp16: h_t, x, h_slot, h_intent

__device__ __forceinline__ uint32_t h2_to_u32(__half2 v) {
    union { __half2 h; uint32_t u; } cvt;
    cvt.h = v;
    return cvt.u;
}

// atile id per k-iteration: kt<12 -> j0 tile of h_t (0..3), kt>=12 -> 4..15
__device__ __host__ __forceinline__ int atile_of(int kt) {
    return (kt < 12) ? (kt / 3) : (4 + (kt - 12));
}

// ---------------- merged prep (512 threads) ----------------
#define A_BLOCKS 8192          // 4 tensors * 2048 (8192 elems per block)
#define W_BLOCKS 288           // 6 g * 24 ktiles * 2 hhalves

__global__ __launch_bounds__(512) void prep_kernel(
    const float* __restrict__ Ws,
    const float* __restrict__ h_t, const float* __restrict__ x,
    const float* __restrict__ h_slot, const float* __restrict__ h_intent)
{
    __shared__ float s[64][133];
    const int bid = blockIdx.x;
    const int tid = threadIdx.x;
    if (bid < A_BLOCKS) {
        const int which = bid >> 11;           // 0..3
        const float* src = (which == 0) ? h_t : (which == 1) ? x
                         : (which == 2) ? h_slot : h_intent;
        __half* dst = g_af + (size_t)which * (TTOK * HD);
        const size_t i = (((size_t)(bid & 2047)) * 512 + tid) * 16;
        float4 v0 = __ldcs((const float4*)(src + i));
        float4 v1 = __ldcs((const float4*)(src + i + 4));
        float4 v2 = __ldcs((const float4*)(src + i + 8));
        float4 v3 = __ldcs((const float4*)(src + i + 12));
        uint4 p0 = make_uint4(h2_to_u32(__floats2half2_rn(v0.x, v0.y)),
                              h2_to_u32(__floats2half2_rn(v0.z, v0.w)),
                              h2_to_u32(__floats2half2_rn(v1.x, v1.y)),
                              h2_to_u32(__floats2half2_rn(v1.z, v1.w)));
        uint4 p1 = make_uint4(h2_to_u32(__floats2half2_rn(v2.x, v2.y)),
                              h2_to_u32(__floats2half2_rn(v2.z, v2.w)),
                              h2_to_u32(__floats2half2_rn(v3.x, v3.y)),
                              h2_to_u32(__floats2half2_rn(v3.z, v3.w)));
        *(uint4*)(dst + i) = p0;
        *(uint4*)(dst + i + 8) = p1;
    } else {
        const int bw = bid - A_BLOCKS;         // 0..287
        const int g  = bw / 48;
        const int rem = bw - g * 48;
        const int kt = rem >> 1;
        const int k0 = kt * 64;
        const int h0 = (rem & 1) * 128;
#pragma unroll
        for (int p = 0; p < 4; p++) {
            int i  = tid + p * 512;            // 2048 float4 loads
            int k  = i >> 5;
            int f4 = i & 31;
            float4 v = __ldcs((const float4*)(Ws + ((size_t)g * KD + k0 + k) * HD + h0 + f4 * 4));
            s[k][f4 * 4 + 0] = v.x;
            s[k][f4 * 4 + 1] = v.y;
            s[k][f4 * 4 + 2] = v.z;
            s[k][f4 * 4 + 3] = v.w;
        }
        __syncthreads();
        const int lane = tid & 31;
        const int wrow = tid >> 5;             // 0..15
#pragma unroll
        for (int p = 0; p < 8; p++) {
            int h = wrow + p * 16;
            int n = (h0 + h) * 6 + g;
            __half2 v = __floats2half2_rn(s[2 * lane][h], s[2 * lane + 1][h]);
            *(__half2*)(g_Wh + (size_t)n * KD + k0 + 2 * lane) = v;
        }
    }
}

// ---------------- helpers ----------------
__device__ __forceinline__ void cp16(uint32_t dst, const void* src, uint32_t sz) {
    asm volatile("cp.async.ca.shared.global [%0], [%1], 16, %2;\n"
                 :: "r"(dst), "l"(src), "r"(sz));
}
__device__ __forceinline__ void cp16f(uint32_t dst, const void* src) {
    asm volatile("cp.async.ca.shared.global [%0], [%1], 16;\n"
                 :: "r"(dst), "l"(src));
}
__device__ __forceinline__ void ldsm4(uint32_t& r0, uint32_t& r1, uint32_t& r2,
                                      uint32_t& r3, uint32_t addr) {
    asm volatile("ldmatrix.sync.aligned.m8n8.x4.shared.b16 {%0,%1,%2,%3}, [%4];"
                 : "=r"(r0), "=r"(r1), "=r"(r2), "=r"(r3) : "r"(addr));
}
__device__ __forceinline__ float tanh_fast(float x) {
    float y;
    asm("tanh.approx.f32 %0, %1;" : "=f"(y) : "f"(x));
    return y;
}
__device__ __forceinline__ float fsig(float v)  { return 0.5f * tanh_fast(0.5f * v) + 0.5f; }

__global__ __launch_bounds__(NTHREADS, 1) void slstm_kernel(
    const float* __restrict__ c_t, const float* __restrict__ bs,
    float* __restrict__ out)
{
    extern __shared__ float smem[];
    const int tid  = threadIdx.x;
    const int warp = tid >> 5;
    const int lane = tid & 31;
    const int wr = warp & 3;           // 4 warp rows (M, 32 each)
    const int wc = warp >> 2;          // 4 warp cols (N, 48 each)
    const int gID = lane >> 2;
    const int t4  = lane & 3;
    const int rowb = blockIdx.y * BM;
    const int nb   = blockIdx.x * BN;
    const int h0t  = blockIdx.x * 32;

    const uint32_t sb = (uint32_t)__cvta_generic_to_shared(smem);

    // bias preload
    {
        float4* bbuf = (float4*)((char*)smem + BIAS_BYTE_OFF);
        const float4* src = (const float4*)bs;
        for (int i = tid; i < 384; i += NTHREADS) bbuf[i] = src[i];
    }

    float acc[2][6][4];
#pragma unroll
    for (int i = 0; i < 2; i++)
#pragma unroll
        for (int j = 0; j < 6; j++)
#pragma unroll
            for (int q = 0; q < 4; q++) acc[i][j][q] = 0.0f;

    // ---- A tile load (ring of 3) ----
    auto issueA = [&](int atile) {
        const uint32_t sA = sb + (uint32_t)((atile % 3) * A_BYTES);
        if (atile < 4) {
            // h_t tile: 130 rows (slots 0..129 = tokens rowb-1 .. rowb+128)
            const int j0 = atile * 64;
            const __half* hb = g_af;       // which = 0
#pragma unroll
            for (int i = 0; i < 3; i++) {
                int idx = tid + i * NTHREADS;
                if (idx < 1040) {
                    int r  = idx >> 3;     // slot 0..129
                    int f4 = idx & 7;
                    bool valid = true;
                    if (r == 0)        valid = (rowb & LMASK) != 0;
                    else if (r == 129) valid = ((rowb + BM) & LMASK) != 0;
                    const __half* src = valid
                        ? (hb + (size_t)(rowb + r - 1) * HD + j0 + f4 * 8)
                        : hb;              // src-size=0 -> zero fill
                    cp16(sA + (uint32_t)(r * ROWB + f4 * 16), src, valid ? 16u : 0u);
                }
            }
        } else {
            // x / h_slot / h_intent tile: 128 rows at slots 1..128
            const int w = atile - 4;       // 0..11
            const int which = 1 + (w >> 2);
            const int j0 = (w & 3) * 64;
            const __half* abase = g_af + (size_t)which * (TTOK * HD);
#pragma unroll
            for (int i = 0; i < 2; i++) {
                int idx = tid + i * NTHREADS;
                int r  = idx >> 3;
                int f4 = idx & 7;
                cp16f(sA + (uint32_t)((r + 1) * ROWB + f4 * 16),
                      abase + (size_t)(rowb + r) * HD + j0 + f4 * 8);
            }
        }
    };

    // ---- B tile load (ring of 3) ----
    auto issueB = [&](int kt) {
        const uint32_t sB = sb + B_RING_OFF + (uint32_t)((kt % 3) * B_BYTES);
        int chunk, j0;
        if (kt < 12) { chunk = kt % 3;            j0 = (kt / 3) * 64; }
        else         { chunk = 3 + ((kt - 12) >> 2); j0 = ((kt - 12) & 3) * 64; }
        const __half* wbase = g_Wh + (size_t)nb * KD + chunk * 256 + j0;
#pragma unroll
        for (int i = 0; i < 3; i++) {
            int idx = tid + i * NTHREADS;
            int r  = idx >> 3;
            int f4 = idx & 7;
            cp16f(sB + (uint32_t)(r * ROWB + f4 * 16),
                  wbase + (size_t)r * KD + f4 * 8);
        }
    };

    // prologue: groups for kt=0 and kt=1
    issueA(0);
    issueB(0);
    asm volatile("cp.async.commit_group;\n");
    issueB(1);                     // atile(1)==atile(0): no A
    asm volatile("cp.async.commit_group;\n");

    // ldmatrix lane addressing (relative to tile base slot)
    const int lj = lane >> 3;
    const int ls = lane & 7;
    const uint32_t a_lane_off =
        (uint32_t)((wr * 32 + (lj & 1) * 8 + ls) * ROWB + (lj >> 1) * 16);
    const uint32_t b_lane_off =
        (uint32_t)((wc * 48 + (lj & 1) * 8 + ls) * ROWB + (lj >> 1) * 16);

#pragma unroll 1
    for (int kt = 0; kt < KITERS; ++kt) {
        asm volatile("cp.async.wait_group 1;\n");
        __syncthreads();
        if (kt + 2 < KITERS) {
            if (atile_of(kt + 2) != atile_of(kt + 1)) issueA(atile_of(kt + 2));
            issueB(kt + 2);
            asm volatile("cp.async.commit_group;\n");
        } else {
            asm volatile("cp.async.commit_group;\n");
        }

        if (kt == KITERS - 6 && tid < 384) {
            int r = tid & 127;
            int sgn = (tid >> 7) - 1;          // -1, 0, 1
            int t = rowb + r + sgn;
            t = (t < 0) ? 0 : (t >= TTOK ? TTOK - 1 : t);
            asm volatile("prefetch.global.L2 [%0];"
                         :: "l"(c_t + (size_t)t * HD + h0t));
        }

        // base slot within the A tile: mid->1, left->0, right->2, non-h->1
        int base_slot = 1;
        if (kt < 12) {
            int chunk = kt % 3;
            base_slot = (chunk == 0) ? 1 : (chunk == 1 ? 0 : 2);
        }
        const uint32_t aA = sb + (uint32_t)((atile_of(kt) % 3) * A_BYTES)
                          + (uint32_t)(base_slot * ROWB) + a_lane_off;
        const uint32_t aB = sb + B_RING_OFF + (uint32_t)((kt % 3) * B_BYTES) + b_lane_off;

        uint32_t a[2][2][4], b[2][6][2];   // [buf][tile][regs]
#pragma unroll
        for (int mt = 0; mt < 2; mt++)
            ldsm4(a[0][mt][0], a[0][mt][1], a[0][mt][2], a[0][mt][3],
                  aA + (uint32_t)(mt * 16 * ROWB));
#pragma unroll
        for (int bt = 0; bt < 3; bt++) {
            uint32_t r0, r1, r2, r3;
            ldsm4(r0, r1, r2, r3, aB + (uint32_t)(bt * 16 * ROWB));
            b[0][2 * bt][0] = r0; b[0][2 * bt + 1][0] = r1;
            b[0][2 * bt][1] = r2; b[0][2 * bt + 1][1] = r3;
        }

#pragma unroll
        for (int ks = 0; ks < 4; ++ks) {       // four k16 steps per BK=64
            const int cur = ks & 1;
            const int nxt = cur ^ 1;
            if (ks < 3) {
                const uint32_t ko = (uint32_t)((ks + 1) * 32);
#pragma unroll
                for (int mt = 0; mt < 2; mt++)
                    ldsm4(a[nxt][mt][0], a[nxt][mt][1], a[nxt][mt][2], a[nxt][mt][3],
                          aA + (uint32_t)(mt * 16 * ROWB) + ko);
#pragma unroll
                for (int bt = 0; bt < 3; bt++) {
                    uint32_t r0, r1, r2, r3;
                    ldsm4(r0, r1, r2, r3, aB + (uint32_t)(bt * 16 * ROWB) + ko);
                    b[nxt][2 * bt][0] = r0; b[nxt][2 * bt + 1][0] = r1;
                    b[nxt][2 * bt][1] = r2; b[nxt][2 * bt + 1][1] = r3;
                }
            }
#pragma unroll
            for (int mt = 0; mt < 2; mt++)
#pragma unroll
                for (int nt = 0; nt < 6; nt++) {
                    asm volatile(
                        "mma.sync.aligned.m16n8k16.row.col.f32.f16.f16.f32 "
                        "{%0,%1,%2,%3}, {%4,%5,%6,%7}, {%8,%9}, {%0,%1,%2,%3};\n"
                        : "+f"(acc[mt][nt][0]), "+f"(acc[mt][nt][1]),
                          "+f"(acc[mt][nt][2]), "+f"(acc[mt][nt][3])
                        : "r"(a[cur][mt][0]), "r"(a[cur][mt][1]),
                          "r"(a[cur][mt][2]), "r"(a[cur][mt][3]),
                          "r"(b[cur][nt][0]), "r"(b[cur][nt][1]));
                }
        }
    }

    asm volatile("cp.async.wait_group 0;\n");
    __syncthreads();

    // stage accumulators: gates[r][h_local][g] (128 rows x 32 h x 8 slots)
    // col pair (c, c+1) has c even -> same h_local = c/6, g = c%6 (even)
    float* gs = smem;
#pragma unroll
    for (int mt = 0; mt < 2; mt++) {
#pragma unroll
        for (int nt = 0; nt < 6; nt++) {
            int r = wr * 32 + mt * 16 + gID;
            int c = wc * 48 + nt * 8 + t4 * 2;
            int off = (c / 6) * 8 + (c % 6);
            *(float2*)(gs + r       * GS2 + off) = make_float2(acc[mt][nt][0], acc[mt][nt][1]);
            *(float2*)(gs + (r + 8) * GS2 + off) = make_float2(acc[mt][nt][2], acc[mt][nt][3]);
        }
    }
    __syncthreads();

    // fused epilogue: each warp handles 8 token rows x 32 h (lane = h_local)
    const float* bb = (const float*)((char*)smem + BIAS_BYTE_OFF);
    const int h = h0t + lane;
    const float b0 = bb[h],        b1 = bb[256 + h],  b2 = bb[512 + h];
    const float b3 = bb[768 + h],  b4 = bb[1024 + h], b5 = bb[1280 + h];
#pragma unroll 2
    for (int it = 0; it < 8; it++) {
        const int r = warp * 8 + it;
        const int t = rowb + r;
        const int l = t & LMASK;
        const float* gp = gs + r * GS2 + lane * 8;
        float4 g03 = *(const float4*)gp;
        float2 g45 = *(const float2*)(gp + 4);
        float cm = c_t[(size_t)t * HD + h];
        float cl = (l != 0)     ? c_t[(size_t)(t - 1) * HD + h] : 0.0f;
        float cr = (l != LMASK) ? c_t[(size_t)(t + 1) * HD + h] : 0.0f;
        float I  = fsig(g03.x + b0);
        float O  = fsig(g03.y + b1);
        float F  = fsig(g03.z + b2);
        float Lg = fsig(g03.w + b3);
        float R  = fsig(g45.x + b4);
        float U  = tanh_fast(g45.y + b5);
        float ei = __expf(I), ef = __expf(F), el = __expf(Lg), er = __expf(R);
        float inv = 1.0f / (ei + ef + el + er);
        float c = (ef * cm + el * cl + er * cr + ei * U) * inv;
        float hn = O * tanh_fast(c);
        out[(size_t)t * HD + h] = hn;
        out[OUT_HALF + (size_t)t * HD + h] = c;
    }
}

// ---------------- launch ----------------
extern "C" void kernel_launch(void* const* d_in, const int* in_sizes, int n_in,
                              void* d_out, int out_size) {
    (void)in_sizes; (void)n_in; (void)out_size;
    const float* h_t      = (const float*)d_in[0];
    const float* x        = (const float*)d_in[1];
    const float* h_slot   = (const float*)d_in[2];
    const float* h_intent = (const float*)d_in[3];
    const float* c_t      = (const float*)d_in[4];
    const float* Ws       = (const float*)d_in[5];
    const float* bs       = (const float*)d_in[6];
    float* out = (float*)d_out;

    cudaFuncSetAttribute(slstm_kernel, cudaFuncAttributeMaxDynamicSharedMemorySize,
                         SMEM_TOTAL);

    prep_kernel<<<A_BLOCKS + W_BLOCKS, 512>>>(Ws, h_t, x, h_slot, h_intent);
    slstm_kernel<<<dim3(NT, MT), NTHREADS, SMEM_TOTAL>>>(c_t, bs, out);
}